// round 1
// baseline (speedup 1.0000x reference)
#include <cuda_runtime.h>
#include <math.h>

// Problem constants
#define BB    64
#define DD    1024
#define LL    2048
#define DH    512          // D/2
#define SPLIT 8
#define LC    (LL / SPLIT) // 256 rows per split

// ---------------- device scratch (no allocations allowed) ----------------
__device__ float g_target[BB * DD];              // input @ W_in^T
__device__ float g_combined[BB * 2 * DD];        // [weightedContext, input]
__device__ float g_acc5[BB * DD];                // pre-tanh accumulator (split-K)
__device__ float g_pm[BB * 2 * SPLIT];           // partial max
__device__ float g_ps[BB * 2 * SPLIT];           // partial sum
__device__ float g_pacc[BB * 2 * SPLIT * DH];    // partial weighted sums
__device__ float g_ms[BB * 2 * 2];               // global (max, 1/sum) per (b,k)

// ---------------- zero the atomic accumulators (every replay) ----------------
__global__ void zero_kernel() {
    int i = blockIdx.x * blockDim.x + threadIdx.x;
    if (i < BB * DD) { g_target[i] = 0.f; g_acc5[i] = 0.f; }
}

// ---------------- split-K NT GEMM: C[m,n] += sum_k A[m,k]*Bw[n,k] -------------
// M = 64 fixed, N = 1024, tiles 64x64, TK = 16, 256 threads, atomic epilogue.
// which==0: A=Ain, C=g_target.  which==1: A=g_combined, C=g_acc5.
__global__ __launch_bounds__(256) void gemm_nt(const float* __restrict__ Ain,
                                               const float* __restrict__ Bw,
                                               int K, int kchunk, int which) {
    const float* A = which ? g_combined : Ain;
    float* C = which ? g_acc5 : g_target;
    const int N = DD;

    __shared__ float As[16][68];
    __shared__ float Bs[16][68];

    int tid  = threadIdx.x;
    int tx   = tid & 15, ty = tid >> 4;
    int lrow = tid >> 2;            // 0..63
    int lcol = (tid & 3) << 2;      // 0,4,8,12
    int n0   = blockIdx.x * 64;
    int k0   = blockIdx.y * kchunk;

    const float* Ap = A  + (size_t)lrow * K + lcol;
    const float* Bp = Bw + (size_t)(n0 + lrow) * K + lcol;

    float acc[4][4];
#pragma unroll
    for (int i = 0; i < 4; i++)
#pragma unroll
        for (int j = 0; j < 4; j++) acc[i][j] = 0.f;

    for (int kk = k0; kk < k0 + kchunk; kk += 16) {
        float4 a = *(const float4*)(Ap + kk);
        float4 b = *(const float4*)(Bp + kk);
        __syncthreads();
        As[lcol + 0][lrow] = a.x; As[lcol + 1][lrow] = a.y;
        As[lcol + 2][lrow] = a.z; As[lcol + 3][lrow] = a.w;
        Bs[lcol + 0][lrow] = b.x; Bs[lcol + 1][lrow] = b.y;
        Bs[lcol + 2][lrow] = b.z; Bs[lcol + 3][lrow] = b.w;
        __syncthreads();
#pragma unroll
        for (int k = 0; k < 16; k++) {
            float4 av = *(const float4*)&As[k][ty << 2];
            float4 bv = *(const float4*)&Bs[k][tx << 2];
            float aa[4] = {av.x, av.y, av.z, av.w};
            float bb[4] = {bv.x, bv.y, bv.z, bv.w};
#pragma unroll
            for (int i = 0; i < 4; i++)
#pragma unroll
                for (int j = 0; j < 4; j++)
                    acc[i][j] = fmaf(aa[i], bb[j], acc[i][j]);
        }
    }
    int row = ty << 2, col = n0 + (tx << 2);
#pragma unroll
    for (int i = 0; i < 4; i++)
#pragma unroll
        for (int j = 0; j < 4; j++)
            atomicAdd(&C[(size_t)(row + i) * N + col + j], acc[i][j]);
}

// ---------------- copy input into second half of combined ----------------
__global__ void copy_input(const float* __restrict__ inp) {
    int b = blockIdx.x;
    for (int i = threadIdx.x; i < DD; i += blockDim.x)
        g_combined[(size_t)b * 2 * DD + DD + i] = inp[(size_t)b * DD + i];
}

// ---------------- fused attention pass (single read of context) ----------------
// grid (SPLIT, B), 256 threads (8 warps). Each warp: online softmax over its rows
// for both queries, register-resident 16-float slice of both 512-wide accumulators.
__global__ __launch_bounds__(256) void attn_pass(const float* __restrict__ ctx,
                                                 float* __restrict__ attn0,
                                                 float* __restrict__ attn1) {
    int b = blockIdx.y, sp = blockIdx.x;
    int tid = threadIdx.x;
    int lane = tid & 31, wid = tid >> 5;

    __shared__ float sQ[DD];
    __shared__ float sm[2][8], ss[2][8];
    __shared__ float sacc[2][DH];

    for (int i = tid; i < DD; i += 256) sQ[i] = g_target[(size_t)b * DD + i];
    for (int i = tid; i < 2 * DH; i += 256) (&sacc[0][0])[i] = 0.f;
    __syncthreads();

    // lane's d indices: d = (lane + 32*j)*4 + t ; targetT[b,d,k] = target[b, 2d+k]
    float q0[16], q1[16];
#pragma unroll
    for (int j = 0; j < 4; j++)
#pragma unroll
        for (int t = 0; t < 4; t++) {
            int d = (lane + 32 * j) * 4 + t;
            q0[j * 4 + t] = sQ[2 * d];
            q1[j * 4 + t] = sQ[2 * d + 1];
        }

    float m0 = -1e30f, m1 = -1e30f, s0 = 0.f, s1 = 0.f;
    float a0[16], a1[16];
#pragma unroll
    for (int i = 0; i < 16; i++) { a0[i] = 0.f; a1[i] = 0.f; }

    const float4* base = (const float4*)(ctx + ((size_t)b * LL + (size_t)sp * LC) * DH);
    const int iters = LC / 8; // 32 rows per warp

    float4 cv[4];
    {
        const float4* row = base + (size_t)wid * (DH / 4);
        cv[0] = row[lane]; cv[1] = row[lane + 32];
        cv[2] = row[lane + 64]; cv[3] = row[lane + 96];
    }

    for (int it = 0; it < iters; it++) {
        float4 nv[4];
        if (it + 1 < iters) {
            const float4* row = base + (size_t)((it + 1) * 8 + wid) * (DH / 4);
            nv[0] = row[lane]; nv[1] = row[lane + 32];
            nv[2] = row[lane + 64]; nv[3] = row[lane + 96];
        }
        float c[16];
#pragma unroll
        for (int j = 0; j < 4; j++) {
            c[4 * j + 0] = cv[j].x; c[4 * j + 1] = cv[j].y;
            c[4 * j + 2] = cv[j].z; c[4 * j + 3] = cv[j].w;
        }
        float d0 = 0.f, d1 = 0.f;
#pragma unroll
        for (int i = 0; i < 16; i++) {
            d0 = fmaf(c[i], q0[i], d0);
            d1 = fmaf(c[i], q1[i], d1);
        }
#pragma unroll
        for (int off = 16; off; off >>= 1) {
            d0 += __shfl_xor_sync(0xffffffffu, d0, off);
            d1 += __shfl_xor_sync(0xffffffffu, d1, off);
        }
        int l = it * 8 + wid;
        if (lane == 0) {
            attn0[(size_t)b * LL + (size_t)sp * LC + l] = d0;  // raw logits, normalized later
            attn1[(size_t)b * LL + (size_t)sp * LC + l] = d1;
        }
        // online softmax, query 0
        float om0 = m0;
        m0 = fmaxf(m0, d0);
        float e0 = __expf(d0 - m0);
        if (om0 < m0) {
            float r = __expf(om0 - m0);
            s0 *= r;
#pragma unroll
            for (int i = 0; i < 16; i++) a0[i] *= r;
        }
        s0 += e0;
#pragma unroll
        for (int i = 0; i < 16; i++) a0[i] = fmaf(e0, c[i], a0[i]);
        // online softmax, query 1
        float om1 = m1;
        m1 = fmaxf(m1, d1);
        float e1 = __expf(d1 - m1);
        if (om1 < m1) {
            float r = __expf(om1 - m1);
            s1 *= r;
#pragma unroll
            for (int i = 0; i < 16; i++) a1[i] *= r;
        }
        s1 += e1;
#pragma unroll
        for (int i = 0; i < 16; i++) a1[i] = fmaf(e1, c[i], a1[i]);

#pragma unroll
        for (int j = 0; j < 4; j++) cv[j] = nv[j];
    }

    // ---- combine 8 warps within the CTA ----
    if (lane == 0) {
        sm[0][wid] = m0; sm[1][wid] = m1;
        ss[0][wid] = s0; ss[1][wid] = s1;
    }
    __syncthreads();
    float M0 = -1e30f, M1 = -1e30f;
#pragma unroll
    for (int w = 0; w < 8; w++) {
        M0 = fmaxf(M0, sm[0][w]);
        M1 = fmaxf(M1, sm[1][w]);
    }
    float f0 = __expf(m0 - M0);
    float f1 = __expf(m1 - M1);
#pragma unroll
    for (int j = 0; j < 4; j++)
#pragma unroll
        for (int t = 0; t < 4; t++) {
            int d = (lane + 32 * j) * 4 + t;
            atomicAdd(&sacc[0][d], a0[j * 4 + t] * f0);
            atomicAdd(&sacc[1][d], a1[j * 4 + t] * f1);
        }
    __syncthreads();

    int idx0 = (b * 2 + 0) * SPLIT + sp;
    int idx1 = (b * 2 + 1) * SPLIT + sp;
    if (tid == 0) {
        float S0 = 0.f, S1 = 0.f;
#pragma unroll
        for (int w = 0; w < 8; w++) {
            S0 += ss[0][w] * __expf(sm[0][w] - M0);
            S1 += ss[1][w] * __expf(sm[1][w] - M1);
        }
        g_pm[idx0] = M0; g_ps[idx0] = S0;
        g_pm[idx1] = M1; g_ps[idx1] = S1;
    }
    for (int i = tid; i < DH; i += 256) {
        g_pacc[(size_t)idx0 * DH + i] = sacc[0][i];
        g_pacc[(size_t)idx1 * DH + i] = sacc[1][i];
    }
}

// ---------------- combine SPLIT partial softmaxes ----------------
__global__ void combine_kernel() {
    int bk = blockIdx.x; // 0..127
    float M = -1e30f;
#pragma unroll
    for (int sp = 0; sp < SPLIT; sp++) M = fmaxf(M, g_pm[bk * SPLIT + sp]);
    float w[SPLIT];
    float S = 0.f;
#pragma unroll
    for (int sp = 0; sp < SPLIT; sp++) {
        w[sp] = __expf(g_pm[bk * SPLIT + sp] - M);
        S += g_ps[bk * SPLIT + sp] * w[sp];
    }
    float inv = 1.0f / S;
    int b = bk >> 1, k = bk & 1;
    for (int d = threadIdx.x; d < DH; d += blockDim.x) {
        float acc = 0.f;
#pragma unroll
        for (int sp = 0; sp < SPLIT; sp++)
            acc += g_pacc[(size_t)(bk * SPLIT + sp) * DH + d] * w[sp];
        g_combined[(size_t)b * 2 * DD + k * DH + d] = acc * inv;
    }
    if (threadIdx.x == 0) { g_ms[bk * 2] = M; g_ms[bk * 2 + 1] = inv; }
}

// ---------------- normalize attn logits in place in d_out ----------------
__global__ void norm_attn(float* __restrict__ out) {
    float* attn0 = out + BB * DD;
    float* attn1 = attn0 + BB * LL;
    int idx = blockIdx.x * blockDim.x + threadIdx.x;
    if (idx >= BB * LL) return;
    int b = idx / LL;
    float M0 = g_ms[(b * 2 + 0) * 2], I0 = g_ms[(b * 2 + 0) * 2 + 1];
    float M1 = g_ms[(b * 2 + 1) * 2], I1 = g_ms[(b * 2 + 1) * 2 + 1];
    attn0[idx] = __expf(attn0[idx] - M0) * I0;
    attn1[idx] = __expf(attn1[idx] - M1) * I1;
}

// ---------------- tanh epilogue ----------------
__global__ void tanh_out(float* __restrict__ out) {
    int i = blockIdx.x * blockDim.x + threadIdx.x;
    if (i < BB * DD) out[i] = tanhf(g_acc5[i]);
}

// ---------------- launcher (graph-capturable, allocation-free) ----------------
extern "C" void kernel_launch(void* const* d_in, const int* in_sizes, int n_in,
                              void* d_out, int out_size) {
    const float* input   = (const float*)d_in[0]; // [64,1024]
    const float* context = (const float*)d_in[1]; // [64,2048,512]
    const float* W_in    = (const float*)d_in[2]; // [1024,1024]
    const float* W_out   = (const float*)d_in[3]; // [1024,2048]
    float* out = (float*)d_out;                   // [ctxOut 65536 | attn0 131072 | attn1 131072]

    zero_kernel<<<(BB * DD + 255) / 256, 256>>>();
    // target = input @ W_in^T  (split-K 8 -> 128 CTAs)
    gemm_nt<<<dim3(DD / 64, 8), 256>>>(input, W_in, DD, DD / 8, 0);
    copy_input<<<BB, 256>>>(input);
    // fused logits + online-softmax weighted sum (single context read)
    attn_pass<<<dim3(SPLIT, BB), 256>>>(context, out + BB * DD, out + BB * DD + BB * LL);
    combine_kernel<<<BB * 2, 128>>>();
    norm_attn<<<(BB * LL + 255) / 256, 256>>>(out);
    // out_pre = combined @ W_out^T  (split-K 8 -> 128 CTAs)
    gemm_nt<<<dim3(DD / 64, 8), 256>>>(nullptr, W_out, 2 * DD, (2 * DD) / 8, 1);
    tanh_out<<<(BB * DD + 255) / 256, 256>>>(out);
}